// round 4
// baseline (speedup 1.0000x reference)
#include <cuda_runtime.h>
#include <math.h>

#define WSR 104   // Whh rows cached in smem (of 152 padded)

// ------------------------------ scratch ------------------------------------
__device__ float g_xp[2][2][400*32*450];     // [seq(ctx=0,q=1)][dir][(t*32+b)*450+g]
__device__ float g_enc[2][400*32*300];       // [(t*32+b)*300 + dir*150+j]
__device__ float g_qa[320*96*300];
__device__ float g_aw[320*96*300];
__device__ float g_xpm[2][96*320*450];       // [(l*320+n)*450+g]
__device__ float g_ans[320*300];
__device__ float g_WihT[2][300*450];
__device__ float g_mWihT[2][300*452];        // padded to 452 cols (last 2 zero)
__device__ float g_WhhT[4][152*450];         // encf,encb,matchf,matchb, zero-padded rows
__device__ float g_WA[300*300], g_WB[300*300], g_WC[300*300];
__device__ float g_cmask[32*400], g_qmask[32*64];
__device__ int   g_qlen[32], g_len[320];

// ------------------------------ prep ---------------------------------------
__global__ void k_prep(const int* ctx, const int* ques,
                       const float* eWihf, const float* eWihb,
                       const float* eWhhf, const float* eWhhb,
                       const float* mWhhf, const float* mWhhb,
                       const float* mWihf, const float* mWihb,
                       const float* fusW) {
    int t0 = blockIdx.x*blockDim.x + threadIdx.x;
    int stride = gridDim.x*blockDim.x;
    for (int i = t0; i < 300*450; i += stride) {
        int e = i/450, g = i%450;
        g_WihT[0][i] = eWihf[g*300+e];
        g_WihT[1][i] = eWihb[g*300+e];
    }
    for (int i = t0; i < 300*452; i += stride) {
        int e = i/452, g = i%452;
        g_mWihT[0][i] = (g < 450) ? mWihf[g*300+e] : 0.f;
        g_mWihT[1][i] = (g < 450) ? mWihb[g*300+e] : 0.f;
    }
    for (int i = t0; i < 152*450; i += stride) {
        int e = i/450, g = i%450;
        float a=0,b=0,c=0,d=0;
        if (e < 150) { a=eWhhf[g*150+e]; b=eWhhb[g*150+e]; c=mWhhf[g*150+e]; d=mWhhb[g*150+e]; }
        g_WhhT[0][i]=a; g_WhhT[1][i]=b; g_WhhT[2][i]=c; g_WhhT[3][i]=d;
    }
    for (int i = t0; i < 300*300; i += stride) {
        int d = i/300, j = i%300;
        const float* r = fusW + (size_t)j*1200;
        float w4 = r[900+d];
        g_WA[i] = r[d] + w4;
        g_WB[i] = r[300+d] - w4;
        g_WC[i] = r[600+d];
    }
    for (int i = t0; i < 32*400; i += stride) g_cmask[i] = (ctx[i]!=0)?1.f:0.f;
    for (int i = t0; i < 32*64;  i += stride) g_qmask[i] = (ques[i]!=0)?1.f:0.f;
    for (int i = t0; i < 32; i += stride) {
        int c=0;
        for (int t=0;t<64;t++) c += (ques[i*64+t]!=0);
        g_qlen[i]=c;
    }
}

// ---------------------- encoder input projections --------------------------
__global__ void k_xp(const int* ctx, const int* ques, const float* emb,
                     const float* bihf, const float* bihb) {
    __shared__ float es[32][304];
    __shared__ int tok[32];
    int t = blockIdx.x;
    int seq = (t >= 400) ? 1 : 0;
    int ti = seq ? t-400 : t;
    int T = seq ? 64 : 400;
    const int* toks = seq ? ques : ctx;
    int tid = threadIdx.x;
    if (tid < 32) tok[tid] = toks[tid*T + ti];
    __syncthreads();
    for (int i = tid; i < 32*300; i += blockDim.x) {
        int b=i/300, e=i%300;
        es[b][e] = emb[(size_t)tok[b]*300 + e];
    }
    __syncthreads();
    int g = tid;
    if (g >= 450) return;
    for (int dir = 0; dir < 2; dir++) {
        const float* WT = g_WihT[dir];
        float bias = (dir ? bihb : bihf)[g];
        float acc[32];
        #pragma unroll
        for (int b=0;b<32;b++) acc[b]=bias;
        for (int e=0;e<300;e+=4) {
            float w0=WT[e*450+g], w1=WT[(e+1)*450+g], w2=WT[(e+2)*450+g], w3=WT[(e+3)*450+g];
            #pragma unroll
            for (int b=0;b<32;b++) {
                float4 v = *(const float4*)&es[b][e];
                acc[b] += w0*v.x + w1*v.y + w2*v.z + w3*v.w;
            }
        }
        float* out = g_xp[seq][dir];
        for (int b=0;b<32;b++) out[((size_t)ti*32+b)*450 + g] = acc[b];
    }
}

// ---------------------------- encoder GRU ----------------------------------
__global__ void k_ernn(const float* bhhf, const float* bhhb) {
    extern __shared__ float sm[];
    float* Wsm = sm;                // 104*450
    float* hsm = sm + WSR*450;      // 152
    float* hgs = hsm + 152;         // 452
    float* xgs = hgs + 452;         // 452
    int id = blockIdx.x;
    int seq = (id >= 64) ? 1 : 0;
    int r = seq ? id-64 : id;
    int dir = r >> 5, b = r & 31;
    int T = seq ? 64 : 400;
    const float* WT = g_WhhT[dir];
    const float* bhh = dir ? bhhb : bhhf;
    const float* xp = g_xp[seq][dir];
    float* out = g_enc[seq];
    const float* mask = seq ? g_qmask : g_cmask;
    int tid = threadIdx.x;
    for (int i = tid; i < WSR*450; i += blockDim.x) Wsm[i] = WT[i];
    for (int i = tid; i < 152; i += blockDim.x) hsm[i] = 0.f;
    __syncthreads();
    int g = tid;
    float bias = (g < 450) ? bhh[g] : 0.f;
    for (int s = 0; s < T; s++) {
        int tt = dir ? (T-1-s) : s;
        if (g < 450) {
            float acc = bias;
            for (int e = 0; e < WSR; e += 4) {
                float4 h4 = *(float4*)&hsm[e];
                acc += h4.x*Wsm[e*450+g] + h4.y*Wsm[(e+1)*450+g]
                     + h4.z*Wsm[(e+2)*450+g] + h4.w*Wsm[(e+3)*450+g];
            }
            for (int e = WSR; e < 152; e += 4) {
                float4 h4 = *(float4*)&hsm[e];
                acc += h4.x*WT[e*450+g] + h4.y*WT[(e+1)*450+g]
                     + h4.z*WT[(e+2)*450+g] + h4.w*WT[(e+3)*450+g];
            }
            hgs[g] = acc;
            xgs[g] = xp[((size_t)tt*32+b)*450 + g];
        }
        __syncthreads();
        if (g < 150) {
            float m = mask[b*T + tt];
            float rr = 1.f/(1.f+expf(-(xgs[g]+hgs[g])));
            float z  = 1.f/(1.f+expf(-(xgs[g+150]+hgs[g+150])));
            float nn = tanhf(xgs[g+300] + rr*hgs[g+300]);
            float hp = hsm[g];
            float hnew = (1.f-z)*nn + z*hp;
            float o = m*hnew;
            hsm[g] = o + (1.f-m)*hp;
            out[((size_t)tt*32+b)*300 + dir*150 + g] = o;
        }
        __syncthreads();
    }
}

// ------------------------------ qa gather ----------------------------------
__global__ void k_gather(const int* ca) {
    int n = blockIdx.x, b = n/10;
    int st = ca[n*2], alen = ca[n*2+1] - st;
    int len = alen + g_qlen[b];
    if (len > 96) len = 96;
    if (threadIdx.x == 0) g_len[n] = len;
    for (int i = threadIdx.x; i < 96*300; i += blockDim.x) {
        int l = i/300, d = i%300;
        float v = 0.f;
        if (l < len) {
            if (l < alen) {
                int t = st + l; if (t > 399) t = 399;
                v = g_enc[0][((size_t)t*32+b)*300 + d];
            } else {
                int t = l - alen; if (t > 63) t = 63;
                v = g_enc[1][((size_t)t*32+b)*300 + d];
            }
        }
        g_qa[((size_t)n*96+l)*300 + d] = v;
    }
}

// ------------------------------ attention ----------------------------------
__global__ void k_attn() {
    extern __shared__ float sm[];
    float* qa_s = sm;              // 32*304
    float* ceT  = sm + 32*304;     // 300*33
    float* sc   = ceT + 300*33;    // 32*400
    int n = blockIdx.x, lt = blockIdx.y, l0 = lt*32;
    if (l0 >= g_len[n]) return;
    int b = n/10;
    int tid = threadIdx.x, warp = tid>>5, lane = tid&31;
    for (int i = tid; i < 32*300; i += 320) {
        int l = i/300, d = i%300;
        qa_s[l*304+d] = g_qa[((size_t)n*96 + l0 + l)*300 + d];
    }
    __syncthreads();
    // pass 1: scores
    for (int t0 = 0; t0 < 400; t0 += 32) {
        int tw = (400 - t0 < 32) ? (400 - t0) : 32;
        for (int i = tid; i < 32*300; i += 320) {
            int t = i/300, d = i%300;
            ceT[d*33+t] = (t < tw) ? g_enc[0][((size_t)(t0+t)*32+b)*300 + d] : 0.f;
        }
        __syncthreads();
        if (warp < 8) {
            int t = lane;
            float a0=0.f,a1=0.f,a2=0.f,a3=0.f;
            int L0=warp, L1=warp+8, L2=warp+16, L3=warp+24;
            for (int d = 0; d < 300; d += 4) {
                float c0=ceT[d*33+t], c1=ceT[(d+1)*33+t], c2=ceT[(d+2)*33+t], c3=ceT[(d+3)*33+t];
                float4 q;
                q = *(float4*)&qa_s[L0*304+d]; a0 += q.x*c0+q.y*c1+q.z*c2+q.w*c3;
                q = *(float4*)&qa_s[L1*304+d]; a1 += q.x*c0+q.y*c1+q.z*c2+q.w*c3;
                q = *(float4*)&qa_s[L2*304+d]; a2 += q.x*c0+q.y*c1+q.z*c2+q.w*c3;
                q = *(float4*)&qa_s[L3*304+d]; a3 += q.x*c0+q.y*c1+q.z*c2+q.w*c3;
            }
            if (t < tw) {
                float cm = g_cmask[b*400 + t0 + t];
                float big = -1e30f;
                sc[L0*400+t0+t] = cm>0.f ? a0 : big;
                sc[L1*400+t0+t] = cm>0.f ? a1 : big;
                sc[L2*400+t0+t] = cm>0.f ? a2 : big;
                sc[L3*400+t0+t] = cm>0.f ? a3 : big;
            }
        }
        __syncthreads();
    }
    // softmax per row
    for (int l = warp; l < 32; l += 10) {
        float mx = -1e30f;
        for (int t = lane; t < 400; t += 32) mx = fmaxf(mx, sc[l*400+t]);
        for (int o = 16; o; o >>= 1) mx = fmaxf(mx, __shfl_xor_sync(0xffffffffu, mx, o));
        float ss = 0.f;
        for (int t = lane; t < 400; t += 32) { float e = expf(sc[l*400+t]-mx); sc[l*400+t]=e; ss += e; }
        for (int o = 16; o; o >>= 1) ss += __shfl_xor_sync(0xffffffffu, ss, o);
        float inv = 1.f/ss;
        for (int t = lane; t < 400; t += 32) sc[l*400+t] *= inv;
    }
    __syncthreads();
    // pass 2: aware
    int d = tid;
    float acc[32];
    #pragma unroll
    for (int l = 0; l < 32; l++) acc[l] = 0.f;
    for (int t0 = 0; t0 < 400; t0 += 32) {
        int tw = (400 - t0 < 32) ? (400 - t0) : 32;
        for (int i = tid; i < 32*300; i += 320) {
            int t = i/300, dd = i%300;
            ceT[dd*33+t] = (t < tw) ? g_enc[0][((size_t)(t0+t)*32+b)*300 + dd] : 0.f;
        }
        __syncthreads();
        if (d < 300) {
            for (int t = 0; t < tw; t += 4) {
                float c0=ceT[d*33+t], c1=ceT[d*33+t+1], c2=ceT[d*33+t+2], c3=ceT[d*33+t+3];
                #pragma unroll
                for (int l = 0; l < 32; l++) {
                    float4 al = *(float4*)&sc[l*400 + t0 + t];
                    acc[l] += al.x*c0 + al.y*c1 + al.z*c2 + al.w*c3;
                }
            }
        }
        __syncthreads();
    }
    if (d < 300)
        for (int l = 0; l < 32; l++)
            g_aw[((size_t)n*96 + l0 + l)*300 + d] = acc[l];
}

// ------------------- fusion GEMM + match input projection ------------------
__global__ void k_fuse(const float* fusb, const float* mbihf, const float* mbihb) {
    extern __shared__ float sm[];
    float* qa_s = sm;               // 16*304
    float* aw_s = sm + 16*304;
    float* qw_s = aw_s + 16*304;
    float* m_s  = qw_s + 16*304;
    int n = blockIdx.x, lt = blockIdx.y, l0 = lt*16;
    if (l0 >= g_len[n]) return;
    int tid = threadIdx.x;
    for (int i = tid; i < 16*300; i += blockDim.x) {
        int l = i/300, d = i%300;
        float q = g_qa[((size_t)n*96 + l0 + l)*300 + d];
        float a = g_aw[((size_t)n*96 + l0 + l)*300 + d];
        qa_s[l*304+d] = q; aw_s[l*304+d] = a; qw_s[l*304+d] = q*a;
    }
    __syncthreads();
    int lg = tid/75, jg = tid%75, j0 = jg*4;
    if (tid < 300) {
        float acc[4][4];
        #pragma unroll
        for (int li=0; li<4; li++)
            #pragma unroll
            for (int j=0; j<4; j++) acc[li][j] = fusb[j0+j];
        for (int d = 0; d < 300; d++) {
            float4 wa = *(float4*)&g_WA[d*300+j0];
            float4 wb = *(float4*)&g_WB[d*300+j0];
            float4 wc = *(float4*)&g_WC[d*300+j0];
            #pragma unroll
            for (int li = 0; li < 4; li++) {
                int l = lg*4 + li;
                float q = qa_s[l*304+d], a = aw_s[l*304+d], w = qw_s[l*304+d];
                acc[li][0] += q*wa.x + a*wb.x + w*wc.x;
                acc[li][1] += q*wa.y + a*wb.y + w*wc.y;
                acc[li][2] += q*wa.z + a*wb.z + w*wc.z;
                acc[li][3] += q*wa.w + a*wb.w + w*wc.w;
            }
        }
        #pragma unroll
        for (int li=0; li<4; li++)
            #pragma unroll
            for (int j=0; j<4; j++)
                m_s[(lg*4+li)*304 + j0 + j] = tanhf(acc[li][j]);
    }
    __syncthreads();
    if (tid < 300) {
        for (int c = 0; c < 4; c++) {
            int grp = c*75 + jg;
            if (grp >= 226) break;
            int jl0 = grp*4;
            int dir = jl0/452, g0 = jl0%452;
            const float* WM = g_mWihT[dir];
            const float* mb = dir ? mbihb : mbihf;
            float acc[4][4];
            #pragma unroll
            for (int li=0; li<4; li++)
                #pragma unroll
                for (int j=0; j<4; j++) acc[li][j] = (g0+j < 450) ? mb[g0+j] : 0.f;
            for (int d = 0; d < 300; d++) {
                float4 w = *(float4*)&WM[d*452 + g0];
                #pragma unroll
                for (int li = 0; li < 4; li++) {
                    float mv = m_s[(lg*4+li)*304 + d];
                    acc[li][0] += mv*w.x; acc[li][1] += mv*w.y;
                    acc[li][2] += mv*w.z; acc[li][3] += mv*w.w;
                }
            }
            #pragma unroll
            for (int li=0; li<4; li++)
                #pragma unroll
                for (int j=0; j<4; j++)
                    if (g0+j < 450)
                        g_xpm[dir][((size_t)(l0+lg*4+li)*320 + n)*450 + g0 + j] = acc[li][j];
        }
    }
}

// ------------------------------ match GRU ----------------------------------
__global__ void k_mrnn(const float* bhhf, const float* bhhb) {
    extern __shared__ float sm[];
    float* Wsm = sm;                 // 104*450
    float* hs  = sm + WSR*450;       // 4*152
    float* hgs = hs + 4*152;         // 4*452
    float* xgs = hgs + 4*452;        // 4*452
    float* rms = xgs + 4*452;        // 4*152
    int dir = blockIdx.x / 80;
    int n0 = (blockIdx.x % 80) * 4;
    const float* WT = g_WhhT[2 + dir];
    const float* bhh = dir ? bhhb : bhhf;
    const float* xp = g_xpm[dir];
    int tid = threadIdx.x;
    for (int i = tid; i < WSR*450; i += blockDim.x) Wsm[i] = WT[i];
    for (int i = tid; i < 4*152; i += blockDim.x) hs[i] = 0.f;
    int lens[4]; int maxlen = 0;
    #pragma unroll
    for (int ni = 0; ni < 4; ni++) { lens[ni] = g_len[n0+ni]; if (lens[ni] > maxlen) maxlen = lens[ni]; }
    for (int i = tid; i < 4*152; i += blockDim.x) {
        int ni = i/152;
        rms[i] = (lens[ni] < 96) ? 0.f : -1e30f;
    }
    __syncthreads();
    int g = tid;
    float bias = (g < 450) ? bhh[g] : 0.f;
    for (int s = 0; s < maxlen; s++) {
        if (g < 450) {
            float a[4];
            #pragma unroll
            for (int ni=0; ni<4; ni++) a[ni] = bias;
            for (int e = 0; e < WSR; e += 4) {
                float w0=Wsm[e*450+g], w1=Wsm[(e+1)*450+g], w2=Wsm[(e+2)*450+g], w3=Wsm[(e+3)*450+g];
                #pragma unroll
                for (int ni = 0; ni < 4; ni++) {
                    float4 h4 = *(float4*)&hs[ni*152 + e];
                    a[ni] += h4.x*w0 + h4.y*w1 + h4.z*w2 + h4.w*w3;
                }
            }
            for (int e = WSR; e < 152; e += 4) {
                float w0=WT[e*450+g], w1=WT[(e+1)*450+g], w2=WT[(e+2)*450+g], w3=WT[(e+3)*450+g];
                #pragma unroll
                for (int ni = 0; ni < 4; ni++) {
                    float4 h4 = *(float4*)&hs[ni*152 + e];
                    a[ni] += h4.x*w0 + h4.y*w1 + h4.z*w2 + h4.w*w3;
                }
            }
            #pragma unroll
            for (int ni = 0; ni < 4; ni++) {
                hgs[ni*452+g] = a[ni];
                int li = dir ? (lens[ni]-1-s) : s;
                if (li < 0) li = 0;
                if (li > 95) li = 95;
                xgs[ni*452+g] = xp[((size_t)li*320 + n0 + ni)*450 + g];
            }
        }
        __syncthreads();
        if (g < 150) {
            #pragma unroll
            for (int ni = 0; ni < 4; ni++) {
                float m = (s < lens[ni]) ? 1.f : 0.f;
                float xr = xgs[ni*452+g], xz = xgs[ni*452+g+150], xn = xgs[ni*452+g+300];
                float hr = hgs[ni*452+g], hz = hgs[ni*452+g+150], hn = hgs[ni*452+g+300];
                float rr = 1.f/(1.f+expf(-(xr+hr)));
                float z  = 1.f/(1.f+expf(-(xz+hz)));
                float nn = tanhf(xn + rr*hn);
                float hp = hs[ni*152+g];
                float hnew = (1.f-z)*nn + z*hp;
                float o = m*hnew;
                hs[ni*152+g] = o + (1.f-m)*hp;
                rms[ni*152+g] = fmaxf(rms[ni*152+g], o);
            }
        }
        __syncthreads();
    }
    if (g < 150)
        for (int ni = 0; ni < 4; ni++)
            g_ans[(n0+ni)*300 + dir*150 + g] = rms[ni*152+g];
}

// ------------------------------ output -------------------------------------
__global__ void k_out(const float* outw, const float* outb, float* out) {
    int b = blockIdx.x, w = threadIdx.x >> 5, lane = threadIdx.x & 31;
    __shared__ float lg[10];
    if (w < 10) {
        int n = b*10 + w;
        float s = 0.f;
        for (int d = lane; d < 300; d += 32) s += g_ans[n*300+d] * outw[d];
        for (int o = 16; o; o >>= 1) s += __shfl_xor_sync(0xffffffffu, s, o);
        if (lane == 0) lg[w] = s + outb[0];
    }
    __syncthreads();
    if (threadIdx.x == 0) {
        float mx = -1e30f;
        for (int k = 0; k < 10; k++) mx = fmaxf(mx, lg[k]);
        float ss = 0.f; float e[10];
        for (int k = 0; k < 10; k++) { e[k] = expf(lg[k]-mx); ss += e[k]; }
        for (int k = 0; k < 10; k++) out[b*10+k] = e[k]/ss;
    }
}

// ------------------------------ launch -------------------------------------
extern "C" void kernel_launch(void* const* d_in, const int* in_sizes, int n_in,
                              void* d_out, int out_size) {
    const int*   ctx   = (const int*)d_in[0];
    const int*   ques  = (const int*)d_in[1];
    const int*   ca    = (const int*)d_in[2];
    const float* emb   = (const float*)d_in[3];
    const float* eWihf = (const float*)d_in[4];
    const float* eWhhf = (const float*)d_in[5];
    const float* ebihf = (const float*)d_in[6];
    const float* ebhhf = (const float*)d_in[7];
    const float* eWihb = (const float*)d_in[8];
    const float* eWhhb = (const float*)d_in[9];
    const float* ebihb = (const float*)d_in[10];
    const float* ebhhb = (const float*)d_in[11];
    const float* mWihf = (const float*)d_in[12];
    const float* mWhhf = (const float*)d_in[13];
    const float* mbihf = (const float*)d_in[14];
    const float* mbhhf = (const float*)d_in[15];
    const float* mWihb = (const float*)d_in[16];
    const float* mWhhb = (const float*)d_in[17];
    const float* mbihb = (const float*)d_in[18];
    const float* mbhhb = (const float*)d_in[19];
    const float* fusW  = (const float*)d_in[20];
    const float* fusb  = (const float*)d_in[21];
    const float* outw  = (const float*)d_in[22];
    const float* outb  = (const float*)d_in[23];

    const int SM_ERNN = (WSR*450 + 152 + 452 + 452) * 4;
    const int SM_ATTN = (32*304 + 300*33 + 32*400) * 4;
    const int SM_FUSE = (4*16*304) * 4;
    const int SM_MRNN = (WSR*450 + 4*152 + 4*452 + 4*452 + 4*152) * 4;
    cudaFuncSetAttribute(k_ernn, cudaFuncAttributeMaxDynamicSharedMemorySize, SM_ERNN);
    cudaFuncSetAttribute(k_attn, cudaFuncAttributeMaxDynamicSharedMemorySize, SM_ATTN);
    cudaFuncSetAttribute(k_fuse, cudaFuncAttributeMaxDynamicSharedMemorySize, SM_FUSE);
    cudaFuncSetAttribute(k_mrnn, cudaFuncAttributeMaxDynamicSharedMemorySize, SM_MRNN);

    k_prep<<<256, 256>>>(ctx, ques, eWihf, eWihb, eWhhf, eWhhb,
                         mWhhf, mWhhb, mWihf, mWihb, fusW);
    k_xp<<<464, 480>>>(ctx, ques, emb, ebihf, ebihb);
    k_ernn<<<128, 480, SM_ERNN>>>(ebhhf, ebhhb);
    k_gather<<<320, 512>>>(ca);
    k_attn<<<dim3(320,3), 320, SM_ATTN>>>();
    k_fuse<<<dim3(320,6), 320, SM_FUSE>>>(fusb, mbihf, mbihb);
    k_mrnn<<<160, 480, SM_MRNN>>>(mbhhf, mbhhb);
    k_out<<<32, 320>>>(outw, outb, (float*)d_out);
}

// round 5
// speedup vs baseline: 1.1995x; 1.1995x over previous
#include <cuda_runtime.h>
#include <math.h>

#define WREG 64    // Whh rows held in registers
#define WSM  88    // Whh rows held in smem (64..151)

// ------------------------------ scratch ------------------------------------
__device__ float g_xp[2][2][400*32*450];     // [seq(ctx=0,q=1)][dir][(t*32+b)*450+g]
__device__ float g_enc[2][400*32*300];       // [(t*32+b)*300 + dir*150+j]
__device__ float g_qa[320*96*300];
__device__ float g_aw[320*96*300];
__device__ float g_xpm[2][96*320*450];       // [(l*320+n)*450+g]
__device__ float g_ans[320*300];
__device__ float g_WihT[2][300*450];
__device__ float g_mWihT[2][300*452];        // padded to 452 cols (last 2 zero)
__device__ float g_WhhT[4][152*450];         // encf,encb,matchf,matchb, zero-padded rows
__device__ float g_WA[300*300], g_WB[300*300], g_WC[300*300];
__device__ float g_cmask[32*400], g_qmask[32*64];
__device__ int   g_qlen[32], g_len[320];

// ------------------------------ prep ---------------------------------------
__global__ void k_prep(const int* ctx, const int* ques,
                       const float* eWihf, const float* eWihb,
                       const float* eWhhf, const float* eWhhb,
                       const float* mWhhf, const float* mWhhb,
                       const float* mWihf, const float* mWihb,
                       const float* fusW) {
    int t0 = blockIdx.x*blockDim.x + threadIdx.x;
    int stride = gridDim.x*blockDim.x;
    for (int i = t0; i < 300*450; i += stride) {
        int e = i/450, g = i%450;
        g_WihT[0][i] = eWihf[g*300+e];
        g_WihT[1][i] = eWihb[g*300+e];
    }
    for (int i = t0; i < 300*452; i += stride) {
        int e = i/452, g = i%452;
        g_mWihT[0][i] = (g < 450) ? mWihf[g*300+e] : 0.f;
        g_mWihT[1][i] = (g < 450) ? mWihb[g*300+e] : 0.f;
    }
    for (int i = t0; i < 152*450; i += stride) {
        int e = i/450, g = i%450;
        float a=0,b=0,c=0,d=0;
        if (e < 150) { a=eWhhf[g*150+e]; b=eWhhb[g*150+e]; c=mWhhf[g*150+e]; d=mWhhb[g*150+e]; }
        g_WhhT[0][i]=a; g_WhhT[1][i]=b; g_WhhT[2][i]=c; g_WhhT[3][i]=d;
    }
    for (int i = t0; i < 300*300; i += stride) {
        int d = i/300, j = i%300;
        const float* r = fusW + (size_t)j*1200;
        float w4 = r[900+d];
        g_WA[i] = r[d] + w4;
        g_WB[i] = r[300+d] - w4;
        g_WC[i] = r[600+d];
    }
    for (int i = t0; i < 32*400; i += stride) g_cmask[i] = (ctx[i]!=0)?1.f:0.f;
    for (int i = t0; i < 32*64;  i += stride) g_qmask[i] = (ques[i]!=0)?1.f:0.f;
    for (int i = t0; i < 32; i += stride) {
        int c=0;
        for (int t=0;t<64;t++) c += (ques[i*64+t]!=0);
        g_qlen[i]=c;
    }
}

// ------------------------ warm (profiling spacer) ---------------------------
__global__ void k_warm() {
    int i = blockIdx.x*blockDim.x + threadIdx.x;
    if (i < 320*300) g_ans[i] = 0.f;
}

// ---------------------- encoder input projections --------------------------
__global__ void k_xp(const int* __restrict__ ctx, const int* __restrict__ ques,
                     const float* __restrict__ emb,
                     const float* __restrict__ bihf, const float* __restrict__ bihb) {
    __shared__ float es[32][304];
    __shared__ int tok[32];
    int t = blockIdx.x;
    int seq = (t >= 400) ? 1 : 0;
    int ti = seq ? t-400 : t;
    int T = seq ? 64 : 400;
    const int* toks = seq ? ques : ctx;
    int tid = threadIdx.x;
    if (tid < 32) tok[tid] = toks[tid*T + ti];
    __syncthreads();
    for (int i = tid; i < 32*300; i += blockDim.x) {
        int b=i/300, e=i%300;
        es[b][e] = emb[(size_t)tok[b]*300 + e];
    }
    __syncthreads();
    int g = tid;
    if (g >= 450) return;
    for (int dir = 0; dir < 2; dir++) {
        const float* __restrict__ WT = g_WihT[dir];
        float bias = (dir ? bihb : bihf)[g];
        float acc[32];
        #pragma unroll
        for (int b=0;b<32;b++) acc[b]=bias;
        for (int e=0;e<300;e+=4) {
            float w0=WT[e*450+g], w1=WT[(e+1)*450+g], w2=WT[(e+2)*450+g], w3=WT[(e+3)*450+g];
            #pragma unroll
            for (int b=0;b<32;b++) {
                float4 v = *(const float4*)&es[b][e];
                acc[b] += w0*v.x + w1*v.y + w2*v.z + w3*v.w;
            }
        }
        float* out = g_xp[seq][dir];
        for (int b=0;b<32;b++) out[((size_t)ti*32+b)*450 + g] = acc[b];
    }
}

// ---------------------------- encoder GRU ----------------------------------
__global__ void __launch_bounds__(480) k_ernn(const float* __restrict__ bhhf,
                                              const float* __restrict__ bhhb) {
    extern __shared__ float sm[];
    float* Wsm = sm;                // 88*450 (rows 64..151)
    float* hsm = sm + WSM*450;      // 152
    float* hgs = hsm + 152;         // 452
    float* xgs = hgs + 452;         // 452
    int id = blockIdx.x;
    int seq = (id >= 64) ? 1 : 0;
    int r = seq ? id-64 : id;
    int dir = r >> 5, b = r & 31;
    int T = seq ? 64 : 400;
    const float* __restrict__ WT = g_WhhT[dir];
    const float* __restrict__ bhh = dir ? bhhb : bhhf;
    const float* __restrict__ xp = g_xp[seq][dir];
    float* out = g_enc[seq];
    const float* __restrict__ mask = seq ? g_qmask : g_cmask;
    int tid = threadIdx.x;
    for (int i = tid; i < WSM*450; i += blockDim.x) Wsm[i] = WT[WREG*450 + i];
    for (int i = tid; i < 152; i += blockDim.x) hsm[i] = 0.f;
    int g = tid;
    float wreg[WREG];
    if (g < 450) {
        #pragma unroll
        for (int e = 0; e < WREG; e++) wreg[e] = WT[e*450 + g];
    }
    __syncthreads();
    float bias = (g < 450) ? bhh[g] : 0.f;
    for (int s = 0; s < T; s++) {
        int tt = dir ? (T-1-s) : s;
        if (g < 450) {
            float acc = bias;
            #pragma unroll
            for (int e = 0; e < WREG; e += 4) {
                float4 h4 = *(float4*)&hsm[e];
                acc += h4.x*wreg[e] + h4.y*wreg[e+1] + h4.z*wreg[e+2] + h4.w*wreg[e+3];
            }
            #pragma unroll
            for (int e = 0; e < WSM; e += 4) {
                float4 h4 = *(float4*)&hsm[WREG + e];
                acc += h4.x*Wsm[e*450+g] + h4.y*Wsm[(e+1)*450+g]
                     + h4.z*Wsm[(e+2)*450+g] + h4.w*Wsm[(e+3)*450+g];
            }
            hgs[g] = acc;
            xgs[g] = xp[((size_t)tt*32+b)*450 + g];
        }
        __syncthreads();
        if (g < 150) {
            float m = mask[b*T + tt];
            float rr = 1.f/(1.f+expf(-(xgs[g]+hgs[g])));
            float z  = 1.f/(1.f+expf(-(xgs[g+150]+hgs[g+150])));
            float nn = tanhf(xgs[g+300] + rr*hgs[g+300]);
            float hp = hsm[g];
            float hnew = (1.f-z)*nn + z*hp;
            float o = m*hnew;
            hsm[g] = o + (1.f-m)*hp;
            out[((size_t)tt*32+b)*300 + dir*150 + g] = o;
        }
        __syncthreads();
    }
}

// ------------------------------ qa gather ----------------------------------
__global__ void k_gather(const int* __restrict__ ca) {
    int n = blockIdx.x, b = n/10;
    int st = ca[n*2], alen = ca[n*2+1] - st;
    int len = alen + g_qlen[b];
    if (len > 96) len = 96;
    if (threadIdx.x == 0) g_len[n] = len;
    for (int i = threadIdx.x; i < 96*300; i += blockDim.x) {
        int l = i/300, d = i%300;
        float v = 0.f;
        if (l < len) {
            if (l < alen) {
                int t = st + l; if (t > 399) t = 399;
                v = g_enc[0][((size_t)t*32+b)*300 + d];
            } else {
                int t = l - alen; if (t > 63) t = 63;
                v = g_enc[1][((size_t)t*32+b)*300 + d];
            }
        }
        g_qa[((size_t)n*96+l)*300 + d] = v;
    }
}

// ------------------------------ attention ----------------------------------
__global__ void k_attn() {
    extern __shared__ float sm[];
    float* qa_s = sm;              // 32*304
    float* ceT  = sm + 32*304;     // 300*33
    float* sc   = ceT + 300*33;    // 32*400
    int n = blockIdx.x, lt = blockIdx.y, l0 = lt*32;
    if (l0 >= g_len[n]) return;
    int b = n/10;
    int tid = threadIdx.x, warp = tid>>5, lane = tid&31;
    for (int i = tid; i < 32*300; i += 320) {
        int l = i/300, d = i%300;
        qa_s[l*304+d] = g_qa[((size_t)n*96 + l0 + l)*300 + d];
    }
    __syncthreads();
    // pass 1: scores
    for (int t0 = 0; t0 < 400; t0 += 32) {
        int tw = (400 - t0 < 32) ? (400 - t0) : 32;
        for (int i = tid; i < 32*300; i += 320) {
            int t = i/300, d = i%300;
            ceT[d*33+t] = (t < tw) ? g_enc[0][((size_t)(t0+t)*32+b)*300 + d] : 0.f;
        }
        __syncthreads();
        if (warp < 8) {
            int t = lane;
            float a0=0.f,a1=0.f,a2=0.f,a3=0.f;
            int L0=warp, L1=warp+8, L2=warp+16, L3=warp+24;
            #pragma unroll 4
            for (int d = 0; d < 300; d += 4) {
                float c0=ceT[d*33+t], c1=ceT[(d+1)*33+t], c2=ceT[(d+2)*33+t], c3=ceT[(d+3)*33+t];
                float4 q;
                q = *(float4*)&qa_s[L0*304+d]; a0 += q.x*c0+q.y*c1+q.z*c2+q.w*c3;
                q = *(float4*)&qa_s[L1*304+d]; a1 += q.x*c0+q.y*c1+q.z*c2+q.w*c3;
                q = *(float4*)&qa_s[L2*304+d]; a2 += q.x*c0+q.y*c1+q.z*c2+q.w*c3;
                q = *(float4*)&qa_s[L3*304+d]; a3 += q.x*c0+q.y*c1+q.z*c2+q.w*c3;
            }
            if (t < tw) {
                float cm = g_cmask[b*400 + t0 + t];
                float big = -1e30f;
                sc[L0*400+t0+t] = cm>0.f ? a0 : big;
                sc[L1*400+t0+t] = cm>0.f ? a1 : big;
                sc[L2*400+t0+t] = cm>0.f ? a2 : big;
                sc[L3*400+t0+t] = cm>0.f ? a3 : big;
            }
        }
        __syncthreads();
    }
    // softmax per row
    for (int l = warp; l < 32; l += 10) {
        float mx = -1e30f;
        for (int t = lane; t < 400; t += 32) mx = fmaxf(mx, sc[l*400+t]);
        for (int o = 16; o; o >>= 1) mx = fmaxf(mx, __shfl_xor_sync(0xffffffffu, mx, o));
        float ss = 0.f;
        for (int t = lane; t < 400; t += 32) { float e = expf(sc[l*400+t]-mx); sc[l*400+t]=e; ss += e; }
        for (int o = 16; o; o >>= 1) ss += __shfl_xor_sync(0xffffffffu, ss, o);
        float inv = 1.f/ss;
        for (int t = lane; t < 400; t += 32) sc[l*400+t] *= inv;
    }
    __syncthreads();
    // pass 2: aware
    int d = tid;
    float acc[32];
    #pragma unroll
    for (int l = 0; l < 32; l++) acc[l] = 0.f;
    for (int t0 = 0; t0 < 400; t0 += 32) {
        int tw = (400 - t0 < 32) ? (400 - t0) : 32;
        for (int i = tid; i < 32*300; i += 320) {
            int t = i/300, dd = i%300;
            ceT[dd*33+t] = (t < tw) ? g_enc[0][((size_t)(t0+t)*32+b)*300 + dd] : 0.f;
        }
        __syncthreads();
        if (d < 300) {
            for (int t = 0; t < tw; t += 4) {
                float c0=ceT[d*33+t], c1=ceT[d*33+t+1], c2=ceT[d*33+t+2], c3=ceT[d*33+t+3];
                #pragma unroll
                for (int l = 0; l < 32; l++) {
                    float4 al = *(float4*)&sc[l*400 + t0 + t];
                    acc[l] += al.x*c0 + al.y*c1 + al.z*c2 + al.w*c3;
                }
            }
        }
        __syncthreads();
    }
    if (d < 300)
        for (int l = 0; l < 32; l++)
            g_aw[((size_t)n*96 + l0 + l)*300 + d] = acc[l];
}

// ------------------- fusion GEMM + match input projection ------------------
__global__ void k_fuse(const float* __restrict__ fusb,
                       const float* __restrict__ mbihf, const float* __restrict__ mbihb) {
    extern __shared__ float sm[];
    float* qa_s = sm;               // 16*304
    float* aw_s = sm + 16*304;
    float* qw_s = aw_s + 16*304;
    float* m_s  = qw_s + 16*304;
    int n = blockIdx.x, lt = blockIdx.y, l0 = lt*16;
    if (l0 >= g_len[n]) return;
    int tid = threadIdx.x;
    for (int i = tid; i < 16*300; i += blockDim.x) {
        int l = i/300, d = i%300;
        float q = g_qa[((size_t)n*96 + l0 + l)*300 + d];
        float a = g_aw[((size_t)n*96 + l0 + l)*300 + d];
        qa_s[l*304+d] = q; aw_s[l*304+d] = a; qw_s[l*304+d] = q*a;
    }
    __syncthreads();
    int lg = tid/75, jg = tid%75, j0 = jg*4;
    if (tid < 300) {
        float acc[4][4];
        #pragma unroll
        for (int li=0; li<4; li++)
            #pragma unroll
            for (int j=0; j<4; j++) acc[li][j] = fusb[j0+j];
        #pragma unroll 4
        for (int d = 0; d < 300; d++) {
            float4 wa = *(const float4*)&g_WA[d*300+j0];
            float4 wb = *(const float4*)&g_WB[d*300+j0];
            float4 wc = *(const float4*)&g_WC[d*300+j0];
            #pragma unroll
            for (int li = 0; li < 4; li++) {
                int l = lg*4 + li;
                float q = qa_s[l*304+d], a = aw_s[l*304+d], w = qw_s[l*304+d];
                acc[li][0] += q*wa.x + a*wb.x + w*wc.x;
                acc[li][1] += q*wa.y + a*wb.y + w*wc.y;
                acc[li][2] += q*wa.z + a*wb.z + w*wc.z;
                acc[li][3] += q*wa.w + a*wb.w + w*wc.w;
            }
        }
        #pragma unroll
        for (int li=0; li<4; li++)
            #pragma unroll
            for (int j=0; j<4; j++)
                m_s[(lg*4+li)*304 + j0 + j] = tanhf(acc[li][j]);
    }
    __syncthreads();
    if (tid < 300) {
        for (int c = 0; c < 4; c++) {
            int grp = c*75 + jg;
            if (grp >= 226) break;
            int jl0 = grp*4;
            int dir = jl0/452, g0 = jl0%452;
            const float* __restrict__ WM = g_mWihT[dir];
            const float* __restrict__ mb = dir ? mbihb : mbihf;
            float acc[4][4];
            #pragma unroll
            for (int li=0; li<4; li++)
                #pragma unroll
                for (int j=0; j<4; j++) acc[li][j] = (g0+j < 450) ? mb[g0+j] : 0.f;
            #pragma unroll 4
            for (int d = 0; d < 300; d++) {
                float4 w = *(const float4*)&WM[d*452 + g0];
                #pragma unroll
                for (int li = 0; li < 4; li++) {
                    float mv = m_s[(lg*4+li)*304 + d];
                    acc[li][0] += mv*w.x; acc[li][1] += mv*w.y;
                    acc[li][2] += mv*w.z; acc[li][3] += mv*w.w;
                }
            }
            #pragma unroll
            for (int li=0; li<4; li++)
                #pragma unroll
                for (int j=0; j<4; j++)
                    if (g0+j < 450)
                        g_xpm[dir][((size_t)(l0+lg*4+li)*320 + n)*450 + g0 + j] = acc[li][j];
        }
    }
}

// ------------------------------ match GRU ----------------------------------
__global__ void __launch_bounds__(480) k_mrnn(const float* __restrict__ bhhf,
                                              const float* __restrict__ bhhb) {
    extern __shared__ float sm[];
    float* Wsm = sm;                 // 88*450 (rows 64..151)
    float* hs  = sm + WSM*450;       // 4*152
    float* hgs = hs + 4*152;         // 4*452
    float* xgs = hgs + 4*452;        // 4*452
    float* rms = xgs + 4*452;        // 4*152
    int dir = blockIdx.x / 80;
    int n0 = (blockIdx.x % 80) * 4;
    const float* __restrict__ WT = g_WhhT[2 + dir];
    const float* __restrict__ bhh = dir ? bhhb : bhhf;
    const float* __restrict__ xp = g_xpm[dir];
    int tid = threadIdx.x;
    for (int i = tid; i < WSM*450; i += blockDim.x) Wsm[i] = WT[WREG*450 + i];
    for (int i = tid; i < 4*152; i += blockDim.x) hs[i] = 0.f;
    int lens[4]; int maxlen = 0;
    #pragma unroll
    for (int ni = 0; ni < 4; ni++) { lens[ni] = g_len[n0+ni]; if (lens[ni] > maxlen) maxlen = lens[ni]; }
    for (int i = tid; i < 4*152; i += blockDim.x) {
        int ni = i/152;
        rms[i] = (lens[ni] < 96) ? 0.f : -1e30f;
    }
    int g = tid;
    float wreg[WREG];
    if (g < 450) {
        #pragma unroll
        for (int e = 0; e < WREG; e++) wreg[e] = WT[e*450 + g];
    }
    __syncthreads();
    float bias = (g < 450) ? bhh[g] : 0.f;
    for (int s = 0; s < maxlen; s++) {
        if (g < 450) {
            float a[4];
            #pragma unroll
            for (int ni=0; ni<4; ni++) a[ni] = bias;
            #pragma unroll
            for (int e = 0; e < WREG; e += 4) {
                #pragma unroll
                for (int ni = 0; ni < 4; ni++) {
                    float4 h4 = *(float4*)&hs[ni*152 + e];
                    a[ni] += h4.x*wreg[e] + h4.y*wreg[e+1] + h4.z*wreg[e+2] + h4.w*wreg[e+3];
                }
            }
            #pragma unroll
            for (int e = 0; e < WSM; e += 4) {
                float w0=Wsm[e*450+g], w1=Wsm[(e+1)*450+g], w2=Wsm[(e+2)*450+g], w3=Wsm[(e+3)*450+g];
                #pragma unroll
                for (int ni = 0; ni < 4; ni++) {
                    float4 h4 = *(float4*)&hs[ni*152 + WREG + e];
                    a[ni] += h4.x*w0 + h4.y*w1 + h4.z*w2 + h4.w*w3;
                }
            }
            #pragma unroll
            for (int ni = 0; ni < 4; ni++) {
                hgs[ni*452+g] = a[ni];
                int li = dir ? (lens[ni]-1-s) : s;
                if (li < 0) li = 0;
                if (li > 95) li = 95;
                xgs[ni*452+g] = xp[((size_t)li*320 + n0 + ni)*450 + g];
            }
        }
        __syncthreads();
        if (g < 150) {
            #pragma unroll
            for (int ni = 0; ni < 4; ni++) {
                float m = (s < lens[ni]) ? 1.f : 0.f;
                float xr = xgs[ni*452+g], xz = xgs[ni*452+g+150], xn = xgs[ni*452+g+300];
                float hr = hgs[ni*452+g], hz = hgs[ni*452+g+150], hn = hgs[ni*452+g+300];
                float rr = 1.f/(1.f+expf(-(xr+hr)));
                float z  = 1.f/(1.f+expf(-(xz+hz)));
                float nn = tanhf(xn + rr*hn);
                float hp = hs[ni*152+g];
                float hnew = (1.f-z)*nn + z*hp;
                float o = m*hnew;
                hs[ni*152+g] = o + (1.f-m)*hp;
                rms[ni*152+g] = fmaxf(rms[ni*152+g], o);
            }
        }
        __syncthreads();
    }
    if (g < 150)
        for (int ni = 0; ni < 4; ni++)
            g_ans[(n0+ni)*300 + dir*150 + g] = rms[ni*152+g];
}

// ------------------------------ output -------------------------------------
__global__ void k_out(const float* __restrict__ outw, const float* __restrict__ outb,
                      float* __restrict__ out) {
    int b = blockIdx.x, w = threadIdx.x >> 5, lane = threadIdx.x & 31;
    __shared__ float lg[10];
    if (w < 10) {
        int n = b*10 + w;
        float s = 0.f;
        for (int d = lane; d < 300; d += 32) s += g_ans[n*300+d] * outw[d];
        for (int o = 16; o; o >>= 1) s += __shfl_xor_sync(0xffffffffu, s, o);
        if (lane == 0) lg[w] = s + outb[0];
    }
    __syncthreads();
    if (threadIdx.x == 0) {
        float mx = -1e30f;
        for (int k = 0; k < 10; k++) mx = fmaxf(mx, lg[k]);
        float ss = 0.f; float e[10];
        for (int k = 0; k < 10; k++) { e[k] = expf(lg[k]-mx); ss += e[k]; }
        for (int k = 0; k < 10; k++) out[b*10+k] = e[k]/ss;
    }
}

// ------------------------------ launch -------------------------------------
extern "C" void kernel_launch(void* const* d_in, const int* in_sizes, int n_in,
                              void* d_out, int out_size) {
    const int*   ctx   = (const int*)d_in[0];
    const int*   ques  = (const int*)d_in[1];
    const int*   ca    = (const int*)d_in[2];
    const float* emb   = (const float*)d_in[3];
    const float* eWihf = (const float*)d_in[4];
    const float* eWhhf = (const float*)d_in[5];
    const float* ebihf = (const float*)d_in[6];
    const float* ebhhf = (const float*)d_in[7];
    const float* eWihb = (const float*)d_in[8];
    const float* eWhhb = (const float*)d_in[9];
    const float* ebihb = (const float*)d_in[10];
    const float* ebhhb = (const float*)d_in[11];
    const float* mWihf = (const float*)d_in[12];
    const float* mWhhf = (const float*)d_in[13];
    const float* mbihf = (const float*)d_in[14];
    const float* mbhhf = (const float*)d_in[15];
    const float* mWihb = (const float*)d_in[16];
    const float* mWhhb = (const float*)d_in[17];
    const float* mbihb = (const float*)d_in[18];
    const float* mbhhb = (const float*)d_in[19];
    const float* fusW  = (const float*)d_in[20];
    const float* fusb  = (const float*)d_in[21];
    const float* outw  = (const float*)d_in[22];
    const float* outb  = (const float*)d_in[23];

    const int SM_ERNN = (WSM*450 + 152 + 452 + 452) * 4;
    const int SM_ATTN = (32*304 + 300*33 + 32*400) * 4;
    const int SM_FUSE = (4*16*304) * 4;
    const int SM_MRNN = (WSM*450 + 4*152 + 4*452 + 4*452 + 4*152) * 4;
    cudaFuncSetAttribute(k_ernn, cudaFuncAttributeMaxDynamicSharedMemorySize, SM_ERNN);
    cudaFuncSetAttribute(k_attn, cudaFuncAttributeMaxDynamicSharedMemorySize, SM_ATTN);
    cudaFuncSetAttribute(k_fuse, cudaFuncAttributeMaxDynamicSharedMemorySize, SM_FUSE);
    cudaFuncSetAttribute(k_mrnn, cudaFuncAttributeMaxDynamicSharedMemorySize, SM_MRNN);

    k_prep<<<256, 256>>>(ctx, ques, eWihf, eWihb, eWhhf, eWhhb,
                         mWhhf, mWhhb, mWihf, mWihb, fusW);
    k_xp<<<464, 480>>>(ctx, ques, emb, ebihf, ebihb);
    k_warm<<<375, 256>>>();
    k_ernn<<<128, 480, SM_ERNN>>>(ebhhf, ebhhb);
    k_gather<<<320, 512>>>(ca);
    k_attn<<<dim3(320,3), 320, SM_ATTN>>>();
    k_fuse<<<dim3(320,6), 320, SM_FUSE>>>(fusb, mbihf, mbihb);
    k_mrnn<<<160, 480, SM_MRNN>>>(mbhhf, mbhhb);
    k_out<<<32, 320>>>(outw, outb, (float*)d_out);
}

// round 6
// speedup vs baseline: 1.2382x; 1.0322x over previous
#include <cuda_runtime.h>
#include <math.h>

#define WREG_E 80  // ernn: Whh rows in registers
#define WSM_E  72  // ernn: Whh rows in smem (80..151)
#define WREG_M 64  // mrnn: rows in registers
#define WSM_M  88  // mrnn: rows in smem

// ------------------------------ scratch ------------------------------------
__device__ float g_xp[2][2][400*32*450];     // [seq(ctx=0,q=1)][dir][(t*32+b)*450+g]
__device__ float g_enc[2][400*32*300];       // [(t*32+b)*300 + dir*150+j]
__device__ float g_qa[320*96*300];
__device__ float g_aw[320*96*300];
__device__ float g_xpm[2][96*320*450];       // [(l*320+n)*450+g]
__device__ float g_ans[320*300];
__device__ float g_WihT[2][300*450];
__device__ float g_mWihT[2][300*452];        // padded to 452 cols (last 2 zero)
__device__ float g_WhhT[4][152*450];         // encf,encb,matchf,matchb, zero-padded rows
__device__ float g_WA[300*300], g_WB[300*300], g_WC[300*300];
__device__ float g_cmask[32*400], g_qmask[32*64];
__device__ int   g_qlen[32], g_len[320];

// ------------------------------ prep ---------------------------------------
__global__ void k_prep(const int* ctx, const int* ques,
                       const float* eWihf, const float* eWihb,
                       const float* eWhhf, const float* eWhhb,
                       const float* mWhhf, const float* mWhhb,
                       const float* mWihf, const float* mWihb,
                       const float* fusW) {
    int t0 = blockIdx.x*blockDim.x + threadIdx.x;
    int stride = gridDim.x*blockDim.x;
    for (int i = t0; i < 300*450; i += stride) {
        int e = i/450, g = i%450;
        g_WihT[0][i] = eWihf[g*300+e];
        g_WihT[1][i] = eWihb[g*300+e];
    }
    for (int i = t0; i < 300*452; i += stride) {
        int e = i/452, g = i%452;
        g_mWihT[0][i] = (g < 450) ? mWihf[g*300+e] : 0.f;
        g_mWihT[1][i] = (g < 450) ? mWihb[g*300+e] : 0.f;
    }
    for (int i = t0; i < 152*450; i += stride) {
        int e = i/450, g = i%450;
        float a=0,b=0,c=0,d=0;
        if (e < 150) { a=eWhhf[g*150+e]; b=eWhhb[g*150+e]; c=mWhhf[g*150+e]; d=mWhhb[g*150+e]; }
        g_WhhT[0][i]=a; g_WhhT[1][i]=b; g_WhhT[2][i]=c; g_WhhT[3][i]=d;
    }
    for (int i = t0; i < 300*300; i += stride) {
        int d = i/300, j = i%300;
        const float* r = fusW + (size_t)j*1200;
        float w4 = r[900+d];
        g_WA[i] = r[d] + w4;
        g_WB[i] = r[300+d] - w4;
        g_WC[i] = r[600+d];
    }
    for (int i = t0; i < 32*400; i += stride) g_cmask[i] = (ctx[i]!=0)?1.f:0.f;
    for (int i = t0; i < 32*64;  i += stride) g_qmask[i] = (ques[i]!=0)?1.f:0.f;
    for (int i = t0; i < 32; i += stride) {
        int c=0;
        for (int t=0;t<64;t++) c += (ques[i*64+t]!=0);
        g_qlen[i]=c;
    }
}

// ------------------------ warm (profiling spacer) ---------------------------
__global__ void k_warm() {
    int i = blockIdx.x*blockDim.x + threadIdx.x;
    if (i < 320*300) g_ans[i] = 0.f;
}

// ---------------------- encoder input projections --------------------------
__global__ void k_xp(const int* __restrict__ ctx, const int* __restrict__ ques,
                     const float* __restrict__ emb,
                     const float* __restrict__ bihf, const float* __restrict__ bihb) {
    __shared__ float es[32][304];
    __shared__ int tok[32];
    int t = blockIdx.x;
    int seq = (t >= 400) ? 1 : 0;
    int ti = seq ? t-400 : t;
    int T = seq ? 64 : 400;
    const int* toks = seq ? ques : ctx;
    int tid = threadIdx.x;
    if (tid < 32) tok[tid] = toks[tid*T + ti];
    __syncthreads();
    for (int i = tid; i < 32*300; i += blockDim.x) {
        int b=i/300, e=i%300;
        es[b][e] = emb[(size_t)tok[b]*300 + e];
    }
    __syncthreads();
    int g = tid;
    if (g >= 450) return;
    for (int dir = 0; dir < 2; dir++) {
        const float* __restrict__ WT = g_WihT[dir];
        float bias = (dir ? bihb : bihf)[g];
        float acc[32];
        #pragma unroll
        for (int b=0;b<32;b++) acc[b]=bias;
        for (int e=0;e<300;e+=4) {
            float w0=WT[e*450+g], w1=WT[(e+1)*450+g], w2=WT[(e+2)*450+g], w3=WT[(e+3)*450+g];
            #pragma unroll
            for (int b=0;b<32;b++) {
                float4 v = *(const float4*)&es[b][e];
                acc[b] += w0*v.x + w1*v.y + w2*v.z + w3*v.w;
            }
        }
        float* out = g_xp[seq][dir];
        for (int b=0;b<32;b++) out[((size_t)ti*32+b)*450 + g] = acc[b];
    }
}

// ---------------------------- encoder GRU ----------------------------------
__global__ void __launch_bounds__(480) k_ernn(const float* __restrict__ bhhf,
                                              const float* __restrict__ bhhb) {
    extern __shared__ float sm[];
    float* Wsm = sm;                  // WSM_E*450 (rows 80..151)
    float* hsm = sm + WSM_E*450;      // 152
    float* hgs = hsm + 152;           // 452
    float* xgs = hgs + 452;           // 452
    int id = blockIdx.x;
    int seq = (id >= 64) ? 1 : 0;
    int r = seq ? id-64 : id;
    int dir = r >> 5, b = r & 31;
    int T = seq ? 64 : 400;
    const float* __restrict__ WT = g_WhhT[dir];
    const float* __restrict__ bhh = dir ? bhhb : bhhf;
    const float* __restrict__ xp = g_xp[seq][dir];
    float* out = g_enc[seq];
    const float* __restrict__ mask = seq ? g_qmask : g_cmask;
    int tid = threadIdx.x;
    for (int i = tid; i < WSM_E*450; i += blockDim.x) Wsm[i] = WT[WREG_E*450 + i];
    for (int i = tid; i < 152; i += blockDim.x) hsm[i] = 0.f;
    int g = tid;
    float wreg[WREG_E];
    if (g < 450) {
        #pragma unroll
        for (int e = 0; e < WREG_E; e++) wreg[e] = WT[e*450 + g];
    }
    __syncthreads();
    float bias = (g < 450) ? bhh[g] : 0.f;
    int tt0 = dir ? (T-1) : 0;
    float xnext = (g < 450) ? xp[((size_t)tt0*32+b)*450 + g] : 0.f;
    for (int s = 0; s < T; s++) {
        int tt = dir ? (T-1-s) : s;
        if (g < 450) {
            float a0=bias, a1=0.f, a2=0.f, a3=0.f;
            #pragma unroll
            for (int e = 0; e < WREG_E; e += 16) {
                float4 h;
                h = *(float4*)&hsm[e];
                a0 += h.x*wreg[e]    + h.y*wreg[e+1]  + h.z*wreg[e+2]  + h.w*wreg[e+3];
                h = *(float4*)&hsm[e+4];
                a1 += h.x*wreg[e+4]  + h.y*wreg[e+5]  + h.z*wreg[e+6]  + h.w*wreg[e+7];
                h = *(float4*)&hsm[e+8];
                a2 += h.x*wreg[e+8]  + h.y*wreg[e+9]  + h.z*wreg[e+10] + h.w*wreg[e+11];
                h = *(float4*)&hsm[e+12];
                a3 += h.x*wreg[e+12] + h.y*wreg[e+13] + h.z*wreg[e+14] + h.w*wreg[e+15];
            }
            #pragma unroll
            for (int e = 0; e < WSM_E; e += 8) {
                float4 h;
                h = *(float4*)&hsm[WREG_E + e];
                a2 += h.x*Wsm[e*450+g]     + h.y*Wsm[(e+1)*450+g]
                    + h.z*Wsm[(e+2)*450+g] + h.w*Wsm[(e+3)*450+g];
                h = *(float4*)&hsm[WREG_E + e + 4];
                a3 += h.x*Wsm[(e+4)*450+g] + h.y*Wsm[(e+5)*450+g]
                    + h.z*Wsm[(e+6)*450+g] + h.w*Wsm[(e+7)*450+g];
            }
            hgs[g] = (a0 + a1) + (a2 + a3);
            xgs[g] = xnext;
        }
        __syncthreads();
        if (s + 1 < T && g < 450) {
            int tn = dir ? (T-2-s) : (s+1);
            xnext = xp[((size_t)tn*32+b)*450 + g];
        }
        if (g < 150) {
            float m = mask[b*T + tt];
            float rr = 1.f/(1.f+expf(-(xgs[g]+hgs[g])));
            float z  = 1.f/(1.f+expf(-(xgs[g+150]+hgs[g+150])));
            float nn = tanhf(xgs[g+300] + rr*hgs[g+300]);
            float hp = hsm[g];
            float hnew = (1.f-z)*nn + z*hp;
            float o = m*hnew;
            hsm[g] = o + (1.f-m)*hp;
            out[((size_t)tt*32+b)*300 + dir*150 + g] = o;
        }
        __syncthreads();
    }
}

// ------------------------------ qa gather ----------------------------------
__global__ void k_gather(const int* __restrict__ ca) {
    int n = blockIdx.x, b = n/10;
    int st = ca[n*2], alen = ca[n*2+1] - st;
    int len = alen + g_qlen[b];
    if (len > 96) len = 96;
    if (threadIdx.x == 0) g_len[n] = len;
    for (int i = threadIdx.x; i < 96*300; i += blockDim.x) {
        int l = i/300, d = i%300;
        float v = 0.f;
        if (l < len) {
            if (l < alen) {
                int t = st + l; if (t > 399) t = 399;
                v = g_enc[0][((size_t)t*32+b)*300 + d];
            } else {
                int t = l - alen; if (t > 63) t = 63;
                v = g_enc[1][((size_t)t*32+b)*300 + d];
            }
        }
        g_qa[((size_t)n*96+l)*300 + d] = v;
    }
}

// ------------------------------ attention ----------------------------------
__global__ void k_attn() {
    extern __shared__ float sm[];
    float* qa_s = sm;              // 32*304
    float* ceT  = sm + 32*304;     // 300*33
    float* sc   = ceT + 300*33;    // 32*400
    int n = blockIdx.x, lt = blockIdx.y, l0 = lt*32;
    if (l0 >= g_len[n]) return;
    int b = n/10;
    int tid = threadIdx.x, warp = tid>>5, lane = tid&31;
    for (int i = tid; i < 32*300; i += 320) {
        int l = i/300, d = i%300;
        qa_s[l*304+d] = g_qa[((size_t)n*96 + l0 + l)*300 + d];
    }
    __syncthreads();
    // pass 1: scores
    for (int t0 = 0; t0 < 400; t0 += 32) {
        int tw = (400 - t0 < 32) ? (400 - t0) : 32;
        for (int i = tid; i < 32*300; i += 320) {
            int t = i/300, d = i%300;
            ceT[d*33+t] = (t < tw) ? g_enc[0][((size_t)(t0+t)*32+b)*300 + d] : 0.f;
        }
        __syncthreads();
        if (warp < 8) {
            int t = lane;
            float a0=0.f,a1=0.f,a2=0.f,a3=0.f;
            int L0=warp, L1=warp+8, L2=warp+16, L3=warp+24;
            #pragma unroll 4
            for (int d = 0; d < 300; d += 4) {
                float c0=ceT[d*33+t], c1=ceT[(d+1)*33+t], c2=ceT[(d+2)*33+t], c3=ceT[(d+3)*33+t];
                float4 q;
                q = *(float4*)&qa_s[L0*304+d]; a0 += q.x*c0+q.y*c1+q.z*c2+q.w*c3;
                q = *(float4*)&qa_s[L1*304+d]; a1 += q.x*c0+q.y*c1+q.z*c2+q.w*c3;
                q = *(float4*)&qa_s[L2*304+d]; a2 += q.x*c0+q.y*c1+q.z*c2+q.w*c3;
                q = *(float4*)&qa_s[L3*304+d]; a3 += q.x*c0+q.y*c1+q.z*c2+q.w*c3;
            }
            if (t < tw) {
                float cm = g_cmask[b*400 + t0 + t];
                float big = -1e30f;
                sc[L0*400+t0+t] = cm>0.f ? a0 : big;
                sc[L1*400+t0+t] = cm>0.f ? a1 : big;
                sc[L2*400+t0+t] = cm>0.f ? a2 : big;
                sc[L3*400+t0+t] = cm>0.f ? a3 : big;
            }
        }
        __syncthreads();
    }
    // softmax per row
    for (int l = warp; l < 32; l += 10) {
        float mx = -1e30f;
        for (int t = lane; t < 400; t += 32) mx = fmaxf(mx, sc[l*400+t]);
        for (int o = 16; o; o >>= 1) mx = fmaxf(mx, __shfl_xor_sync(0xffffffffu, mx, o));
        float ss = 0.f;
        for (int t = lane; t < 400; t += 32) { float e = expf(sc[l*400+t]-mx); sc[l*400+t]=e; ss += e; }
        for (int o = 16; o; o >>= 1) ss += __shfl_xor_sync(0xffffffffu, ss, o);
        float inv = 1.f/ss;
        for (int t = lane; t < 400; t += 32) sc[l*400+t] *= inv;
    }
    __syncthreads();
    // pass 2: aware
    int d = tid;
    float acc[32];
    #pragma unroll
    for (int l = 0; l < 32; l++) acc[l] = 0.f;
    for (int t0 = 0; t0 < 400; t0 += 32) {
        int tw = (400 - t0 < 32) ? (400 - t0) : 32;
        for (int i = tid; i < 32*300; i += 320) {
            int t = i/300, dd = i%300;
            ceT[dd*33+t] = (t < tw) ? g_enc[0][((size_t)(t0+t)*32+b)*300 + dd] : 0.f;
        }
        __syncthreads();
        if (d < 300) {
            for (int t = 0; t < tw; t += 4) {
                float c0=ceT[d*33+t], c1=ceT[d*33+t+1], c2=ceT[d*33+t+2], c3=ceT[d*33+t+3];
                #pragma unroll
                for (int l = 0; l < 32; l++) {
                    float4 al = *(float4*)&sc[l*400 + t0 + t];
                    acc[l] += al.x*c0 + al.y*c1 + al.z*c2 + al.w*c3;
                }
            }
        }
        __syncthreads();
    }
    if (d < 300)
        for (int l = 0; l < 32; l++)
            g_aw[((size_t)n*96 + l0 + l)*300 + d] = acc[l];
}

// ------------------- fusion GEMM + match input projection ------------------
__global__ void k_fuse(const float* __restrict__ fusb,
                       const float* __restrict__ mbihf, const float* __restrict__ mbihb) {
    extern __shared__ float sm[];
    float* qa_s = sm;               // 16*304
    float* aw_s = sm + 16*304;
    float* qw_s = aw_s + 16*304;
    float* m_s  = qw_s + 16*304;
    int n = blockIdx.x, lt = blockIdx.y, l0 = lt*16;
    if (l0 >= g_len[n]) return;
    int tid = threadIdx.x;
    for (int i = tid; i < 16*300; i += blockDim.x) {
        int l = i/300, d = i%300;
        float q = g_qa[((size_t)n*96 + l0 + l)*300 + d];
        float a = g_aw[((size_t)n*96 + l0 + l)*300 + d];
        qa_s[l*304+d] = q; aw_s[l*304+d] = a; qw_s[l*304+d] = q*a;
    }
    __syncthreads();
    int lg = tid/75, jg = tid%75, j0 = jg*4;
    if (tid < 300) {
        float acc[4][4];
        #pragma unroll
        for (int li=0; li<4; li++)
            #pragma unroll
            for (int j=0; j<4; j++) acc[li][j] = fusb[j0+j];
        #pragma unroll 4
        for (int d = 0; d < 300; d++) {
            float4 wa = *(const float4*)&g_WA[d*300+j0];
            float4 wb = *(const float4*)&g_WB[d*300+j0];
            float4 wc = *(const float4*)&g_WC[d*300+j0];
            #pragma unroll
            for (int li = 0; li < 4; li++) {
                int l = lg*4 + li;
                float q = qa_s[l*304+d], a = aw_s[l*304+d], w = qw_s[l*304+d];
                acc[li][0] += q*wa.x + a*wb.x + w*wc.x;
                acc[li][1] += q*wa.y + a*wb.y + w*wc.y;
                acc[li][2] += q*wa.z + a*wb.z + w*wc.z;
                acc[li][3] += q*wa.w + a*wb.w + w*wc.w;
            }
        }
        #pragma unroll
        for (int li=0; li<4; li++)
            #pragma unroll
            for (int j=0; j<4; j++)
                m_s[(lg*4+li)*304 + j0 + j] = tanhf(acc[li][j]);
    }
    __syncthreads();
    if (tid < 300) {
        for (int c = 0; c < 4; c++) {
            int grp = c*75 + jg;
            if (grp >= 226) break;
            int jl0 = grp*4;
            int dir = jl0/452, g0 = jl0%452;
            const float* __restrict__ WM = g_mWihT[dir];
            const float* __restrict__ mb = dir ? mbihb : mbihf;
            float acc[4][4];
            #pragma unroll
            for (int li=0; li<4; li++)
                #pragma unroll
                for (int j=0; j<4; j++) acc[li][j] = (g0+j < 450) ? mb[g0+j] : 0.f;
            #pragma unroll 4
            for (int d = 0; d < 300; d++) {
                float4 w = *(const float4*)&WM[d*452 + g0];
                #pragma unroll
                for (int li = 0; li < 4; li++) {
                    float mv = m_s[(lg*4+li)*304 + d];
                    acc[li][0] += mv*w.x; acc[li][1] += mv*w.y;
                    acc[li][2] += mv*w.z; acc[li][3] += mv*w.w;
                }
            }
            #pragma unroll
            for (int li=0; li<4; li++)
                #pragma unroll
                for (int j=0; j<4; j++)
                    if (g0+j < 450)
                        g_xpm[dir][((size_t)(l0+lg*4+li)*320 + n)*450 + g0 + j] = acc[li][j];
        }
    }
}

// ------------------------------ match GRU ----------------------------------
__global__ void __launch_bounds__(480) k_mrnn(const float* __restrict__ bhhf,
                                              const float* __restrict__ bhhb) {
    extern __shared__ float sm[];
    float* Wsm = sm;                   // WSM_M*450 (rows 64..151)
    float* hs  = sm + WSM_M*450;       // 4*152
    float* hgs = hs + 4*152;           // 4*452
    float* xgs = hgs + 4*452;          // 4*452
    float* rms = xgs + 4*452;          // 4*152
    int dir = blockIdx.x / 80;
    int n0 = (blockIdx.x % 80) * 4;
    const float* __restrict__ WT = g_WhhT[2 + dir];
    const float* __restrict__ bhh = dir ? bhhb : bhhf;
    const float* __restrict__ xp = g_xpm[dir];
    int tid = threadIdx.x;
    for (int i = tid; i < WSM_M*450; i += blockDim.x) Wsm[i] = WT[WREG_M*450 + i];
    for (int i = tid; i < 4*152; i += blockDim.x) hs[i] = 0.f;
    int lens[4]; int maxlen = 0;
    #pragma unroll
    for (int ni = 0; ni < 4; ni++) { lens[ni] = g_len[n0+ni]; if (lens[ni] > maxlen) maxlen = lens[ni]; }
    for (int i = tid; i < 4*152; i += blockDim.x) {
        int ni = i/152;
        rms[i] = (lens[ni] < 96) ? 0.f : -1e30f;
    }
    int g = tid;
    float wreg[WREG_M];
    if (g < 450) {
        #pragma unroll
        for (int e = 0; e < WREG_M; e++) wreg[e] = WT[e*450 + g];
    }
    __syncthreads();
    float bias = (g < 450) ? bhh[g] : 0.f;
    float xnx[4];
    if (g < 450) {
        #pragma unroll
        for (int ni = 0; ni < 4; ni++) {
            int li = dir ? (lens[ni]-1) : 0;
            if (li < 0) li = 0;
            if (li > 95) li = 95;
            xnx[ni] = xp[((size_t)li*320 + n0 + ni)*450 + g];
        }
    }
    for (int s = 0; s < maxlen; s++) {
        if (g < 450) {
            float a[4];
            #pragma unroll
            for (int ni=0; ni<4; ni++) a[ni] = bias;
            #pragma unroll
            for (int e = 0; e < WREG_M; e += 4) {
                #pragma unroll
                for (int ni = 0; ni < 4; ni++) {
                    float4 h4 = *(float4*)&hs[ni*152 + e];
                    a[ni] += h4.x*wreg[e] + h4.y*wreg[e+1] + h4.z*wreg[e+2] + h4.w*wreg[e+3];
                }
            }
            #pragma unroll
            for (int e = 0; e < WSM_M; e += 4) {
                float w0=Wsm[e*450+g], w1=Wsm[(e+1)*450+g], w2=Wsm[(e+2)*450+g], w3=Wsm[(e+3)*450+g];
                #pragma unroll
                for (int ni = 0; ni < 4; ni++) {
                    float4 h4 = *(float4*)&hs[ni*152 + WREG_M + e];
                    a[ni] += h4.x*w0 + h4.y*w1 + h4.z*w2 + h4.w*w3;
                }
            }
            #pragma unroll
            for (int ni = 0; ni < 4; ni++) {
                hgs[ni*452+g] = a[ni];
                xgs[ni*452+g] = xnx[ni];
            }
        }
        __syncthreads();
        if (s + 1 < maxlen && g < 450) {
            #pragma unroll
            for (int ni = 0; ni < 4; ni++) {
                int li = dir ? (lens[ni]-2-s) : (s+1);
                if (li < 0) li = 0;
                if (li > 95) li = 95;
                xnx[ni] = xp[((size_t)li*320 + n0 + ni)*450 + g];
            }
        }
        if (g < 150) {
            #pragma unroll
            for (int ni = 0; ni < 4; ni++) {
                float m = (s < lens[ni]) ? 1.f : 0.f;
                float xr = xgs[ni*452+g], xz = xgs[ni*452+g+150], xn = xgs[ni*452+g+300];
                float hr = hgs[ni*452+g], hz = hgs[ni*452+g+150], hn = hgs[ni*452+g+300];
                float rr = 1.f/(1.f+expf(-(xr+hr)));
                float z  = 1.f/(1.f+expf(-(xz+hz)));
                float nn = tanhf(xn + rr*hn);
                float hp = hs[ni*152+g];
                float hnew = (1.f-z)*nn + z*hp;
                float o = m*hnew;
                hs[ni*152+g] = o + (1.f-m)*hp;
                rms[ni*152+g] = fmaxf(rms[ni*152+g], o);
            }
        }
        __syncthreads();
    }
    if (g < 150)
        for (int ni = 0; ni < 4; ni++)
            g_ans[(n0+ni)*300 + dir*150 + g] = rms[ni*152+g];
}

// ------------------------------ output -------------------------------------
__global__ void k_out(const float* __restrict__ outw, const float* __restrict__ outb,
                      float* __restrict__ out) {
    int b = blockIdx.x, w = threadIdx.x >> 5, lane = threadIdx.x & 31;
    __shared__ float lg[10];
    if (w < 10) {
        int n = b*10 + w;
        float s = 0.f;
        for (int d = lane; d < 300; d += 32) s += g_ans[n*300+d] * outw[d];
        for (int o = 16; o; o >>= 1) s += __shfl_xor_sync(0xffffffffu, s, o);
        if (lane == 0) lg[w] = s + outb[0];
    }
    __syncthreads();
    if (threadIdx.x == 0) {
        float mx = -1e30f;
        for (int k = 0; k < 10; k++) mx = fmaxf(mx, lg[k]);
        float ss = 0.f; float e[10];
        for (int k = 0; k < 10; k++) { e[k] = expf(lg[k]-mx); ss += e[k]; }
        for (int k = 0; k < 10; k++) out[b*10+k] = e[k]/ss;
    }
}

// ------------------------------ launch -------------------------------------
extern "C" void kernel_launch(void* const* d_in, const int* in_sizes, int n_in,
                              void* d_out, int out_size) {
    const int*   ctx   = (const int*)d_in[0];
    const int*   ques  = (const int*)d_in[1];
    const int*   ca    = (const int*)d_in[2];
    const float* emb   = (const float*)d_in[3];
    const float* eWihf = (const float*)d_in[4];
    const float* eWhhf = (const float*)d_in[5];
    const float* ebihf = (const float*)d_in[6];
    const float* ebhhf = (const float*)d_in[7];
    const float* eWihb = (const float*)d_in[8];
    const float* eWhhb = (const float*)d_in[9];
    const float* ebihb = (const float*)d_in[10];
    const float* ebhhb = (const float*)d_in[11];
    const float* mWihf = (const float*)d_in[12];
    const float* mWhhf = (const float*)d_in[13];
    const float* mbihf = (const float*)d_in[14];
    const float* mbhhf = (const float*)d_in[15];
    const float* mWihb = (const float*)d_in[16];
    const float* mWhhb = (const float*)d_in[17];
    const float* mbihb = (const float*)d_in[18];
    const float* mbhhb = (const float*)d_in[19];
    const float* fusW  = (const float*)d_in[20];
    const float* fusb  = (const float*)d_in[21];
    const float* outw  = (const float*)d_in[22];
    const float* outb  = (const float*)d_in[23];

    const int SM_ERNN = (WSM_E*450 + 152 + 452 + 452) * 4;
    const int SM_ATTN = (32*304 + 300*33 + 32*400) * 4;
    const int SM_FUSE = (4*16*304) * 4;
    const int SM_MRNN = (WSM_M*450 + 4*152 + 4*452 + 4*452 + 4*152) * 4;
    cudaFuncSetAttribute(k_ernn, cudaFuncAttributeMaxDynamicSharedMemorySize, SM_ERNN);
    cudaFuncSetAttribute(k_attn, cudaFuncAttributeMaxDynamicSharedMemorySize, SM_ATTN);
    cudaFuncSetAttribute(k_fuse, cudaFuncAttributeMaxDynamicSharedMemorySize, SM_FUSE);
    cudaFuncSetAttribute(k_mrnn, cudaFuncAttributeMaxDynamicSharedMemorySize, SM_MRNN);

    k_prep<<<256, 256>>>(ctx, ques, eWihf, eWihb, eWhhf, eWhhb,
                         mWhhf, mWhhb, mWihf, mWihb, fusW);
    k_xp<<<464, 480>>>(ctx, ques, emb, ebihf, ebihb);
    k_warm<<<375, 256>>>();
    k_ernn<<<128, 480, SM_ERNN>>>(ebhhf, ebhhb);
    k_gather<<<320, 512>>>(ca);
    k_attn<<<dim3(320,3), 320, SM_ATTN>>>();
    k_fuse<<<dim3(320,6), 320, SM_FUSE>>>(fusb, mbihf, mbihb);
    k_mrnn<<<160, 480, SM_MRNN>>>(mbhhf, mbhhb);
    k_out<<<32, 320>>>(outw, outb, (float*)d_out);
}